// round 1
// baseline (speedup 1.0000x reference)
#include <cuda_runtime.h>
#include <math.h>

#define HID 4544
#define NH  71
#define HP  72      // heads padded
#define HD  64
#define NU  32      // users
#define NC  4       // kv chunks
#define SS  2048    // chunk length
#define NQKV 4672   // (NH+2)*HD
#define KSPLIT 4
#define KLEN 1152   // 1152*3 + 1088 = 4544, all multiples of 32

// ---------------- scratch (device globals; no runtime alloc) ----------------
__device__ float g_HT[HID * NU];            // hidden transposed [k][u]
__device__ float g_qkvp[KSPLIT * NU * NQKV];
__device__ float g_qT[NU * HD * HP];        // rotated+scaled q, [u][d][h]
__device__ float g_kcur[NU * HD];
__device__ float g_vcur[NU * HD];
__device__ float g_scur[NU * HP];
__device__ float g_m[NU * 8 * HP];
__device__ float g_l[NU * 8 * HP];
__device__ float g_po[(size_t)NU * 8 * HP * HD];
__device__ float g_attnT[HID * NU];         // attn output transposed [k][u]
__device__ float g_dpart[KSPLIT * NU * HID];

// ---------------- prep: transpose hidden ----------------
__global__ void k_prep(const float* __restrict__ h) {
    int idx = blockIdx.x * blockDim.x + threadIdx.x;
    if (idx < HID * NU) {
        int u = idx / HID, k = idx % HID;
        g_HT[k * NU + u] = h[idx];
    }
}

// ---------------- skinny GEMM: P[ky][u][r] = sum_k T[k][u] * W[r][k] --------
// block: 256 thr; tile 128 rows x 32 users; k tiles of 32 (K, KLEN mult of 32)
__global__ void __launch_bounds__(256) k_gemm32(
    const float* __restrict__ T, const float* __restrict__ W,
    float* __restrict__ P, int N, int K, int klen)
{
    __shared__ float Wt[32 * 132];  // [kk][row]
    __shared__ float Hs[32 * 36];   // [kk][user]
    int t  = threadIdx.x;
    int tx = t >> 5;                // 0..7 user group
    int ty = t & 31;                // 0..31 row group
    int r0 = blockIdx.x * 128;
    int ks = blockIdx.y * klen;
    int ke = min(ks + klen, K);

    float acc[4][4];
#pragma unroll
    for (int i = 0; i < 4; i++)
#pragma unroll
        for (int j = 0; j < 4; j++) acc[i][j] = 0.f;

    int lr = t >> 3, lq = t & 7;
    for (int k0 = ks; k0 < ke; k0 += 32) {
#pragma unroll
        for (int i = 0; i < 4; i++) {
            int r = r0 + lr + 32 * i;
            float4 w = make_float4(0.f, 0.f, 0.f, 0.f);
            if (r < N) w = *(const float4*)(W + (size_t)r * K + k0 + 4 * lq);
            int rr = lr + 32 * i;
            Wt[(4 * lq + 0) * 132 + rr] = w.x;
            Wt[(4 * lq + 1) * 132 + rr] = w.y;
            Wt[(4 * lq + 2) * 132 + rr] = w.z;
            Wt[(4 * lq + 3) * 132 + rr] = w.w;
        }
        {
            int kk = t >> 3, uq = t & 7;
            float4 hv = *(const float4*)(T + (size_t)(k0 + kk) * NU + 4 * uq);
            *(float4*)(Hs + kk * 36 + 4 * uq) = hv;
        }
        __syncthreads();
#pragma unroll
        for (int kk = 0; kk < 32; kk++) {
            float4 hv4 = *(const float4*)(Hs + kk * 36 + 4 * tx);
            float4 wv4 = *(const float4*)(Wt + kk * 132 + 4 * ty);
            float hv[4] = {hv4.x, hv4.y, hv4.z, hv4.w};
            float wv[4] = {wv4.x, wv4.y, wv4.z, wv4.w};
#pragma unroll
            for (int i = 0; i < 4; i++)
#pragma unroll
                for (int j = 0; j < 4; j++) acc[i][j] += wv[i] * hv[j];
        }
        __syncthreads();
    }
    if (r0 + 4 * ty < N) {
        float* base = P + (size_t)blockIdx.y * NU * N;
#pragma unroll
        for (int j = 0; j < 4; j++) {
            float4 v = make_float4(acc[0][j], acc[1][j], acc[2][j], acc[3][j]);
            *(float4*)(base + (size_t)(4 * tx + j) * N + r0 + 4 * ty) = v;
        }
    }
}

// ---------------- post-QKV: reduce partials, rotary, s_cur ----------------
__global__ void __launch_bounds__(256) k_postqkv(
    const float* __restrict__ cosp, const float* __restrict__ sinp)
{
    __shared__ float fr[NQKV];
    __shared__ float sq[HD * HP];
    __shared__ float skc[HD];
    int u = blockIdx.x, t = threadIdx.x;

    for (int r = t; r < NQKV; r += 256) {
        float s = 0.f;
#pragma unroll
        for (int p = 0; p < KSPLIT; p++)
            s += g_qkvp[(size_t)p * NU * NQKV + (size_t)u * NQKV + r];
        fr[r] = s;
    }
    __syncthreads();

    for (int idx = t; idx < HP * HD; idx += 256) {
        int hh = idx / HD, d = idx % HD;
        float val = 0.f;
        if (hh < NH) {
            float q     = fr[hh * HD + d];
            float other = fr[hh * HD + ((d < 32) ? d + 32 : d - 32)];
            float rot   = (d < 32) ? -other : other;
            val = (q * cosp[u * HD + d] + rot * sinp[u * HD + d]) * 0.125f;
        }
        sq[d * HP + hh] = val;
        g_qT[(size_t)u * HD * HP + d * HP + hh] = val;
    }
    if (t < HD) {
        int d = t;
        float kraw   = fr[NH * HD + d];
        float kother = fr[NH * HD + ((d < 32) ? d + 32 : d - 32)];
        float krot   = (d < 32) ? -kother : kother;
        float kc = kraw * cosp[u * HD + d] + krot * sinp[u * HD + d];
        skc[d] = kc;
        g_kcur[u * HD + d] = kc;
        g_vcur[u * HD + d] = fr[(NH + 1) * HD + d];
    }
    __syncthreads();
    if (t < HP) {
        float a = 0.f;
        for (int d = 0; d < HD; d++) a += sq[d * HP + t] * skc[d];
        g_scur[u * HP + t] = a;
    }
}

// ---------------- flash-decode attention partials ----------------
// grid (u=32, c=4, z=2); block 288 = 18 (head groups of 4) x 16 (s/d groups of 4)
#define ATT_SMEM ((HD * HP + 64 * 68 + 64 * 68 + 64 * 76 + 64) * 4)
__global__ void __launch_bounds__(288) k_attn(
    const float* __restrict__ kc, const float* __restrict__ vc,
    const float* __restrict__ mask)
{
    extern __shared__ float sm[];
    float* qTs = sm;                    // [d][hp] 64*72
    float* Kt  = qTs + HD * HP;         // [d][s]  64*68 (pad)
    float* Vs  = Kt + 64 * 68;          // [s][d]  64*68 (pad)
    float* PT  = Vs + 64 * 68;          // [s][hp] 64*76 (pad)
    float* ms  = PT + 64 * 76;          // [s]

    int u = blockIdx.x, c = blockIdx.y, z = blockIdx.z;
    int t = threadIdx.x;
    int hy = t >> 4, sx = t & 15;       // 16-lane groups stay within a half-warp

    for (int i = t; i < HD * HP; i += 288) qTs[i] = g_qT[(size_t)u * HD * HP + i];

    const float* Kg = kc + (((size_t)c * NU + u) * SS + (size_t)z * 1024) * HD;
    const float* Vg = vc + (((size_t)c * NU + u) * SS + (size_t)z * 1024) * HD;
    const float* Mg = mask + ((size_t)c * NU + u) * SS + (size_t)z * 1024;

    float m_run[4], l_run[4], oacc[4][4];
#pragma unroll
    for (int i = 0; i < 4; i++) {
        m_run[i] = -1e30f; l_run[i] = 0.f;
#pragma unroll
        for (int j = 0; j < 4; j++) oacc[i][j] = 0.f;
    }

    for (int tt = 0; tt < 16; tt++) {
        int soff = tt * 64;
        for (int q4 = t; q4 < 1024; q4 += 288) {
            int s = q4 >> 4, dq = q4 & 15;
            float4 kv = *(const float4*)(Kg + (size_t)(soff + s) * HD + 4 * dq);
            Kt[(4 * dq + 0) * 68 + s] = kv.x;
            Kt[(4 * dq + 1) * 68 + s] = kv.y;
            Kt[(4 * dq + 2) * 68 + s] = kv.z;
            Kt[(4 * dq + 3) * 68 + s] = kv.w;
            float4 vv = *(const float4*)(Vg + (size_t)(soff + s) * HD + 4 * dq);
            *(float4*)(Vs + s * 68 + 4 * dq) = vv;
        }
        if (t < 64) ms[t] = Mg[soff + t];
        __syncthreads();

        // GEMM1: scores p[i][j] = q[4hy+i][:] . K[:][4sx+j]
        float p[4][4];
#pragma unroll
        for (int i = 0; i < 4; i++)
#pragma unroll
            for (int j = 0; j < 4; j++) p[i][j] = 0.f;
#pragma unroll 8
        for (int d = 0; d < 64; d++) {
            float4 qv4 = *(const float4*)(qTs + d * HP + 4 * hy);
            float4 kv4 = *(const float4*)(Kt + d * 68 + 4 * sx);
            float qv[4] = {qv4.x, qv4.y, qv4.z, qv4.w};
            float kv[4] = {kv4.x, kv4.y, kv4.z, kv4.w};
#pragma unroll
            for (int i = 0; i < 4; i++)
#pragma unroll
                for (int j = 0; j < 4; j++) p[i][j] += qv[i] * kv[j];
        }
#pragma unroll
        for (int j = 0; j < 4; j++) {
            float mj = ms[4 * sx + j];
#pragma unroll
            for (int i = 0; i < 4; i++) p[i][j] += mj;
        }

        // online softmax update (per head, reduced across the 16-lane group)
#pragma unroll
        for (int i = 0; i < 4; i++) {
            float tm = fmaxf(fmaxf(p[i][0], p[i][1]), fmaxf(p[i][2], p[i][3]));
#pragma unroll
            for (int off = 8; off; off >>= 1)
                tm = fmaxf(tm, __shfl_xor_sync(0xffffffffu, tm, off));
            float mn  = fmaxf(m_run[i], tm);
            float fac = __expf(m_run[i] - mn);
            m_run[i] = mn;
            l_run[i] *= fac;
#pragma unroll
            for (int j = 0; j < 4; j++) oacc[i][j] *= fac;
            float ls = 0.f;
#pragma unroll
            for (int j = 0; j < 4; j++) { p[i][j] = __expf(p[i][j] - mn); ls += p[i][j]; }
#pragma unroll
            for (int off = 8; off; off >>= 1)
                ls += __shfl_xor_sync(0xffffffffu, ls, off);
            l_run[i] += ls;
        }
#pragma unroll
        for (int i = 0; i < 4; i++)
#pragma unroll
            for (int j = 0; j < 4; j++)
                PT[(4 * sx + j) * 76 + 4 * hy + i] = p[i][j];
        __syncwarp();

        // GEMM2: oacc[i][j] += P[4hy+i][s] * V[s][4sx+j]
#pragma unroll 8
        for (int s = 0; s < 64; s++) {
            float4 pv4 = *(const float4*)(PT + s * 76 + 4 * hy);
            float4 vv4 = *(const float4*)(Vs + s * 68 + 4 * sx);
            float pv[4] = {pv4.x, pv4.y, pv4.z, pv4.w};
            float vv[4] = {vv4.x, vv4.y, vv4.z, vv4.w};
#pragma unroll
            for (int i = 0; i < 4; i++)
#pragma unroll
                for (int j = 0; j < 4; j++) oacc[i][j] += pv[i] * vv[j];
        }
        __syncthreads();
    }

    int cz = c * 2 + z;
    size_t sb = ((size_t)(u * 8 + cz) * HP + 4 * hy) * HD;
#pragma unroll
    for (int i = 0; i < 4; i++) {
        float4 v = make_float4(oacc[i][0], oacc[i][1], oacc[i][2], oacc[i][3]);
        *(float4*)(g_po + sb + (size_t)i * HD + 4 * sx) = v;
    }
    if (sx == 0) {
#pragma unroll
        for (int i = 0; i < 4; i++) {
            g_m[(u * 8 + cz) * HP + 4 * hy + i] = m_run[i];
            g_l[(u * 8 + cz) * HP + 4 * hy + i] = l_run[i];
        }
    }
}

// ---------------- combine partials + current token ----------------
__global__ void k_combine() {
    int u = blockIdx.x, hh = blockIdx.y;  // hh < 71
    int d = threadIdx.x;
    float scur = g_scur[u * HP + hh];
    float g = scur;
    float mv[8];
#pragma unroll
    for (int cz = 0; cz < 8; cz++) {
        mv[cz] = g_m[(u * 8 + cz) * HP + hh];
        g = fmaxf(g, mv[cz]);
    }
    float num = 0.f, den = 0.f;
#pragma unroll
    for (int cz = 0; cz < 8; cz++) {
        float w = __expf(mv[cz] - g);
        num += w * g_po[((size_t)(u * 8 + cz) * HP + hh) * HD + d];
        den += w * g_l[(u * 8 + cz) * HP + hh];
    }
    float wc = __expf(scur - g);
    num += wc * g_vcur[u * HD + d];
    den += wc;
    g_attnT[(hh * HD + d) * NU + u] = num / den;
}

// ---------------- final reduce of dense partials ----------------
__global__ void k_reduce_out(float* __restrict__ out) {
    int idx = blockIdx.x * blockDim.x + threadIdx.x;
    if (idx < NU * HID) {
        float s = 0.f;
#pragma unroll
        for (int p = 0; p < KSPLIT; p++)
            s += g_dpart[(size_t)p * NU * HID + idx];
        out[idx] = s;
    }
}

// ---------------- launch ----------------
extern "C" void kernel_launch(void* const* d_in, const int* in_sizes, int n_in,
                              void* d_out, int out_size)
{
    const float* hidden = (const float*)d_in[0];
    const float* cosp   = (const float*)d_in[1];
    const float* sinp   = (const float*)d_in[2];
    const float* kcache = (const float*)d_in[3];
    const float* vcache = (const float*)d_in[4];
    const float* masks  = (const float*)d_in[5];
    const float* w_qkv  = (const float*)d_in[6];
    const float* w_den  = (const float*)d_in[7];
    float* out = (float*)d_out;

    float *p_qkvp, *p_dpart;
    cudaGetSymbolAddress((void**)&p_qkvp, g_qkvp);
    cudaGetSymbolAddress((void**)&p_dpart, g_dpart);

    cudaFuncSetAttribute(k_attn, cudaFuncAttributeMaxDynamicSharedMemorySize, ATT_SMEM);

    k_prep<<<(HID * NU + 255) / 256, 256>>>(hidden);

    float *p_HT, *p_attnT;
    cudaGetSymbolAddress((void**)&p_HT, g_HT);
    cudaGetSymbolAddress((void**)&p_attnT, g_attnT);

    k_gemm32<<<dim3(37, KSPLIT), 256>>>(p_HT, w_qkv, p_qkvp, NQKV, HID, KLEN);
    k_postqkv<<<NU, 256>>>(cosp, sinp);
    k_attn<<<dim3(NU, NC, 2), 288, ATT_SMEM>>>(kcache, vcache, masks);
    k_combine<<<dim3(NU, NH), HD>>>();
    k_gemm32<<<dim3(36, KSPLIT), 256>>>(p_attnT, w_den, p_dpart, HID, HID, KLEN);
    k_reduce_out<<<(NU * HID + 255) / 256, 256>>>(out);
}